// round 1
// baseline (speedup 1.0000x reference)
#include <cuda_runtime.h>

// Shapes (fixed by the problem)
#define B_  4
#define N_  128
#define M_  128
#define D_  256
#define BD_ 1024

// Scratch (no cudaMalloc allowed)
__device__ float g_Aprime[D_ * D_];        // 256 KB: A'[d,e] = sum_k A[d,e,k]*W[k]
__device__ float g_T[B_ * N_ * D_];        // 512 KB: T[r,e] = X[r,:] @ A'

// ---------------------------------------------------------------------------
// Kernel 1: A'[row] = dot(A[row, 0:1024], W[0:1024]); row = d*256 + e.
// One warp per row; 8x float4 per lane; warp shuffle reduction.
// 268 MB streaming read — this is the HBM-bound kernel that dominates runtime.
// ---------------------------------------------------------------------------
__global__ __launch_bounds__(256) void k1_fold_w(
    const float4* __restrict__ A4,   // [65536 rows][256 float4]
    const float4* __restrict__ W4,   // [256 float4]
    float* __restrict__ Ap)          // [65536]
{
    int warp = (blockIdx.x * blockDim.x + threadIdx.x) >> 5;   // 0..65535
    int lane = threadIdx.x & 31;
    const float4* row = A4 + (size_t)warp * (BD_ / 4);

    float s = 0.0f;
#pragma unroll
    for (int i = 0; i < 8; ++i) {
        float4 a = row[lane + i * 32];
        float4 w = W4[lane + i * 32];
        s += a.x * w.x + a.y * w.y;
        s += a.z * w.z + a.w * w.w;
    }
#pragma unroll
    for (int o = 16; o > 0; o >>= 1)
        s += __shfl_xor_sync(0xFFFFFFFFu, s, o);
    if (lane == 0) Ap[warp] = s;
}

// ---------------------------------------------------------------------------
// Kernel 2: T[r,e] = sum_d X[r,d] * A'[d,e].  r in [0,512), e in [0,256).
// One block per r (256 threads, thread = e). A' (256 KB) is L2-resident after
// kernel 1; reads are coalesced across e.
// ---------------------------------------------------------------------------
__global__ __launch_bounds__(256) void k2_xa(
    const float* __restrict__ X,     // [512, 256]
    const float* __restrict__ Ap,    // [256, 256]
    float* __restrict__ T)           // [512, 256]
{
    int r = blockIdx.x;
    int e = threadIdx.x;
    __shared__ float xs[D_];
    xs[e] = X[(size_t)r * D_ + e];
    __syncthreads();

    float s = 0.0f;
#pragma unroll 8
    for (int d = 0; d < D_; ++d)
        s = fmaf(xs[d], Ap[(size_t)d * D_ + e], s);
    T[(size_t)r * D_ + e] = s;
}

// ---------------------------------------------------------------------------
// Kernel 3: S[b,n,m] = sum_e T[b*128+n, e] * Y[b,m,e] + bias.
// One block per (b,n), 128 threads (thread = m). T row cached in smem;
// Y (512 KB) is L2-resident; float4 loads per thread.
// ---------------------------------------------------------------------------
__global__ __launch_bounds__(128) void k3_ty(
    const float* __restrict__ T,     // [512, 256]
    const float* __restrict__ Y,     // [B, 128, 256]
    const float* __restrict__ bias,  // [1]
    float* __restrict__ S)           // [B, 128, 128]
{
    int bn = blockIdx.x;             // 0..511 ; b = bn>>7, n = bn&127
    int m  = threadIdx.x;            // 0..127
    int b  = bn >> 7;

    __shared__ float ts[D_];
    ts[m]        = T[(size_t)bn * D_ + m];
    ts[m + 128]  = T[(size_t)bn * D_ + m + 128];
    __syncthreads();

    const float4* y4 = (const float4*)(Y + ((size_t)b * M_ + m) * D_);
    float s = 0.0f;
#pragma unroll
    for (int i = 0; i < D_ / 4; ++i) {
        float4 y = y4[i];
        s = fmaf(ts[4 * i + 0], y.x, s);
        s = fmaf(ts[4 * i + 1], y.y, s);
        s = fmaf(ts[4 * i + 2], y.z, s);
        s = fmaf(ts[4 * i + 3], y.w, s);
    }
    S[(size_t)bn * M_ + m] = s + bias[0];
}

// ---------------------------------------------------------------------------
extern "C" void kernel_launch(void* const* d_in, const int* in_sizes, int n_in,
                              void* d_out, int out_size)
{
    const float* X  = (const float*)d_in[0];   // [4,128,256]
    const float* Y  = (const float*)d_in[1];   // [4,128,256]
    const float* A  = (const float*)d_in[2];   // [256,256,1024]
    const float* W  = (const float*)d_in[3];   // [1,1024]
    const float* bb = (const float*)d_in[4];   // [1]
    float* S = (float*)d_out;                  // [4,128,128]

    float* Ap;  cudaGetSymbolAddress((void**)&Ap, g_Aprime);
    float* T;   cudaGetSymbolAddress((void**)&T,  g_T);

    // K1: 65536 rows, 1 warp each, 8 warps/block -> 8192 blocks
    k1_fold_w<<<(D_ * D_) / 8, 256>>>((const float4*)A, (const float4*)W, Ap);
    // K2: 512 rows
    k2_xa<<<B_ * N_, 256>>>(X, Ap, T);
    // K3: 512 (b,n) blocks
    k3_ty<<<B_ * N_, 128>>>(T, Y, bb, S);
}

// round 2
// speedup vs baseline: 1.0772x; 1.0772x over previous
#include <cuda_runtime.h>

// Shapes (fixed by the problem)
#define B_  4
#define N_  128
#define M_  128
#define D_  256
#define BD_ 1024

// Scratch (no cudaMalloc allowed)
__device__ float g_Aprime[D_ * D_];        // 256 KB: A'[d,e] = sum_k A[d,e,k]*W[k]
__device__ float g_T[B_ * N_ * D_];        // 512 KB: T[r,e] = X[r,:] @ A'

// ---------------------------------------------------------------------------
// Kernel 1: A'[row] = dot(A[row, :], W[:]); row = d*256 + e.
// One warp per row; 8x float4 per lane; warp shuffle reduction.
// 268 MB streaming read — HBM-bound, dominates runtime. __ldcs keeps the
// one-shot A stream evict-first in L2; W staged in smem (read 8x per thread).
// ---------------------------------------------------------------------------
__global__ __launch_bounds__(256) void k1_fold_w(
    const float4* __restrict__ A4,   // [65536 rows][256 float4]
    const float4* __restrict__ W4,   // [256 float4]
    float* __restrict__ Ap)          // [65536]
{
    __shared__ float4 ws[BD_ / 4];   // 4 KB
    ws[threadIdx.x] = W4[threadIdx.x];
    __syncthreads();

    int warp = (blockIdx.x * blockDim.x + threadIdx.x) >> 5;   // 0..65535
    int lane = threadIdx.x & 31;
    const float4* row = A4 + (size_t)warp * (BD_ / 4);

    float s = 0.0f;
#pragma unroll
    for (int i = 0; i < 8; ++i) {
        float4 a = __ldcs(&row[lane + i * 32]);
        float4 w = ws[lane + i * 32];
        s += a.x * w.x + a.y * w.y;
        s += a.z * w.z + a.w * w.w;
    }
#pragma unroll
    for (int o = 16; o > 0; o >>= 1)
        s += __shfl_xor_sync(0xFFFFFFFFu, s, o);
    if (lane == 0) Ap[warp] = s;
}

// ---------------------------------------------------------------------------
// Kernel 2: T[r,e] = sum_d X[r,d] * A'[d,e].
// 4 r-rows per block (128 blocks, 256 threads = e). X tile in smem (float4),
// 4 accumulators per thread -> A' is read only 128x (32 MB L2 traffic, was
// 131 MB), 4 FMA per A' load.
// ---------------------------------------------------------------------------
__global__ __launch_bounds__(256) void k2_xa(
    const float4* __restrict__ X4,   // [512, 64] float4
    const float* __restrict__ Ap,    // [256, 256]
    float* __restrict__ T)           // [512, 256]
{
    int r0 = blockIdx.x * 4;         // 4 rows per block
    int e  = threadIdx.x;            // 0..255

    __shared__ float4 xs[4][D_ / 4]; // 4 rows x 256 floats = 4 KB
    {
        int ri = e >> 6, c = e & 63;
        xs[ri][c] = X4[(size_t)(r0 + ri) * (D_ / 4) + c];
    }
    __syncthreads();

    float s0 = 0.f, s1 = 0.f, s2 = 0.f, s3 = 0.f;
#pragma unroll 8
    for (int d4 = 0; d4 < D_ / 4; ++d4) {
        int d = d4 * 4;
        float a0 = Ap[(size_t)(d + 0) * D_ + e];
        float a1 = Ap[(size_t)(d + 1) * D_ + e];
        float a2 = Ap[(size_t)(d + 2) * D_ + e];
        float a3 = Ap[(size_t)(d + 3) * D_ + e];
        float4 x0 = xs[0][d4], x1 = xs[1][d4], x2 = xs[2][d4], x3 = xs[3][d4];
        s0 = fmaf(x0.x, a0, s0); s0 = fmaf(x0.y, a1, s0);
        s0 = fmaf(x0.z, a2, s0); s0 = fmaf(x0.w, a3, s0);
        s1 = fmaf(x1.x, a0, s1); s1 = fmaf(x1.y, a1, s1);
        s1 = fmaf(x1.z, a2, s1); s1 = fmaf(x1.w, a3, s1);
        s2 = fmaf(x2.x, a0, s2); s2 = fmaf(x2.y, a1, s2);
        s2 = fmaf(x2.z, a2, s2); s2 = fmaf(x2.w, a3, s2);
        s3 = fmaf(x3.x, a0, s3); s3 = fmaf(x3.y, a1, s3);
        s3 = fmaf(x3.z, a2, s3); s3 = fmaf(x3.w, a3, s3);
    }
    T[(size_t)(r0 + 0) * D_ + e] = s0;
    T[(size_t)(r0 + 1) * D_ + e] = s1;
    T[(size_t)(r0 + 2) * D_ + e] = s2;
    T[(size_t)(r0 + 3) * D_ + e] = s3;
}

// ---------------------------------------------------------------------------
// Kernel 3: S[r,m] = sum_e T[r,e] * Y[b,m,e] + bias,  r = b*128+n.
// 4 r-rows per block (128 blocks, 128 threads = m). T tile in smem as float4,
// per thread one contiguous Y row via float4 -> Y L2 traffic 16 MB (was 67).
// ---------------------------------------------------------------------------
__global__ __launch_bounds__(128) void k3_ty(
    const float4* __restrict__ T4,   // [512, 64] float4
    const float4* __restrict__ Y4,   // [B*128, 64] float4
    const float* __restrict__ bias,  // [1]
    float* __restrict__ S)           // [512, 128]
{
    int r0 = blockIdx.x * 4;         // 4 (b,n) rows per block, same b
    int b  = r0 >> 7;
    int m  = threadIdx.x;            // 0..127

    __shared__ float4 ts[4][D_ / 4]; // 4 KB
#pragma unroll
    for (int j = 0; j < 2; ++j) {
        int idx = m + j * 128;       // 0..255
        int ri = idx >> 6, c = idx & 63;
        ts[ri][c] = T4[(size_t)(r0 + ri) * (D_ / 4) + c];
    }
    __syncthreads();

    const float4* y = Y4 + (size_t)(b * M_ + m) * (D_ / 4);
    float s0 = 0.f, s1 = 0.f, s2 = 0.f, s3 = 0.f;
#pragma unroll 8
    for (int i = 0; i < D_ / 4; ++i) {
        float4 yv = y[i];
        float4 t0 = ts[0][i], t1 = ts[1][i], t2 = ts[2][i], t3 = ts[3][i];
        s0 = fmaf(t0.x, yv.x, s0); s0 = fmaf(t0.y, yv.y, s0);
        s0 = fmaf(t0.z, yv.z, s0); s0 = fmaf(t0.w, yv.w, s0);
        s1 = fmaf(t1.x, yv.x, s1); s1 = fmaf(t1.y, yv.y, s1);
        s1 = fmaf(t1.z, yv.z, s1); s1 = fmaf(t1.w, yv.w, s1);
        s2 = fmaf(t2.x, yv.x, s2); s2 = fmaf(t2.y, yv.y, s2);
        s2 = fmaf(t2.z, yv.z, s2); s2 = fmaf(t2.w, yv.w, s2);
        s3 = fmaf(t3.x, yv.x, s3); s3 = fmaf(t3.y, yv.y, s3);
        s3 = fmaf(t3.z, yv.z, s3); s3 = fmaf(t3.w, yv.w, s3);
    }
    float bb = bias[0];
    S[(size_t)(r0 + 0) * M_ + m] = s0 + bb;
    S[(size_t)(r0 + 1) * M_ + m] = s1 + bb;
    S[(size_t)(r0 + 2) * M_ + m] = s2 + bb;
    S[(size_t)(r0 + 3) * M_ + m] = s3 + bb;
}

// ---------------------------------------------------------------------------
extern "C" void kernel_launch(void* const* d_in, const int* in_sizes, int n_in,
                              void* d_out, int out_size)
{
    const float* X  = (const float*)d_in[0];   // [4,128,256]
    const float* Y  = (const float*)d_in[1];   // [4,128,256]
    const float* A  = (const float*)d_in[2];   // [256,256,1024]
    const float* W  = (const float*)d_in[3];   // [1,1024]
    const float* bb = (const float*)d_in[4];   // [1]
    float* S = (float*)d_out;                  // [4,128,128]

    float* Ap;  cudaGetSymbolAddress((void**)&Ap, g_Aprime);
    float* T;   cudaGetSymbolAddress((void**)&T,  g_T);

    // K1: 65536 rows, 1 warp each, 8 warps/block -> 8192 blocks
    k1_fold_w<<<(D_ * D_) / 8, 256>>>((const float4*)A, (const float4*)W, Ap);
    // K2: 512 rows, 4 per block
    k2_xa<<<(B_ * N_) / 4, 256>>>((const float4*)X, Ap, T);
    // K3: 512 (b,n) rows, 4 per block
    k3_ty<<<(B_ * N_) / 4, 128>>>((const float4*)T, (const float4*)Y, bb, S);
}

// round 3
// speedup vs baseline: 1.1817x; 1.0971x over previous
#include <cuda_runtime.h>

// Shapes (fixed by the problem)
#define B_  4
#define N_  128
#define M_  128
#define D_  256
#define BD_ 1024

// Scratch (no cudaMalloc allowed)
__device__ float g_Aprime[D_ * D_];        // 256 KB: A'[d,e] = sum_k A[d,e,k]*W[k]

// ---------------------------------------------------------------------------
// Kernel 1: A'[row] = dot(A[row, :], W[:]); row = d*256 + e.
// TWO rows per warp -> 16 float4 loads in flight per lane. __ldcs keeps the
// one-shot 268 MB A stream evict-first; W staged in smem.
// ---------------------------------------------------------------------------
__global__ __launch_bounds__(256) void k1_fold_w(
    const float4* __restrict__ A4,   // [65536 rows][256 float4]
    const float4* __restrict__ W4,   // [256 float4]
    float* __restrict__ Ap)          // [65536]
{
    __shared__ float4 ws[BD_ / 4];   // 4 KB
    ws[threadIdx.x] = W4[threadIdx.x];
    __syncthreads();

    int warp = (blockIdx.x * blockDim.x + threadIdx.x) >> 5;   // 0..32767
    int lane = threadIdx.x & 31;
    const float4* row0 = A4 + (size_t)(2 * warp) * (BD_ / 4);
    const float4* row1 = row0 + (BD_ / 4);

    float s0 = 0.0f, s1 = 0.0f;
#pragma unroll
    for (int i = 0; i < 8; ++i) {
        float4 a0 = __ldcs(&row0[lane + i * 32]);
        float4 a1 = __ldcs(&row1[lane + i * 32]);
        float4 w  = ws[lane + i * 32];
        s0 += a0.x * w.x + a0.y * w.y + a0.z * w.z + a0.w * w.w;
        s1 += a1.x * w.x + a1.y * w.y + a1.z * w.z + a1.w * w.w;
    }
#pragma unroll
    for (int o = 16; o > 0; o >>= 1) {
        s0 += __shfl_xor_sync(0xFFFFFFFFu, s0, o);
        s1 += __shfl_xor_sync(0xFFFFFFFFu, s1, o);
    }
    if (lane == 0) {
        Ap[2 * warp + 0] = s0;
        Ap[2 * warp + 1] = s1;
    }
}

// ---------------------------------------------------------------------------
// Fused kernel 2+3: per block, 4 r-rows (same b).
//   Stage A: T_tile[4][256] = X_tile @ A'   (A' from L2, 32 MB total traffic)
//   Stage B: S_tile[4][128] = T_tile @ Y[b]^T   (T from smem, Y 16 MB L2)
// No global T round trip, one launch instead of two.
// ---------------------------------------------------------------------------
__global__ __launch_bounds__(256) void k23_fused(
    const float4* __restrict__ X4,   // [512, 64] float4
    const float* __restrict__ Ap,    // [256, 256]
    const float4* __restrict__ Y4,   // [B*128, 64] float4
    const float* __restrict__ bias,  // [1]
    float* __restrict__ S)           // [512, 128]
{
    int r0 = blockIdx.x * 4;         // rows r0..r0+3, all within one b
    int b  = r0 >> 7;
    int t  = threadIdx.x;            // 0..255

    __shared__ float4 xs[4][D_ / 4];   // 4 KB  X tile
    __shared__ float4 ts4[4][D_ / 4];  // 4 KB  T tile
    float* ts = (float*)ts4;

    {   // cooperative X tile load
        int ri = t >> 6, c = t & 63;
        xs[ri][c] = X4[(size_t)(r0 + ri) * (D_ / 4) + c];
    }
    __syncthreads();

    // ---- Stage A: thread t = column e; 4 row accumulators ----
    {
        float s0 = 0.f, s1 = 0.f, s2 = 0.f, s3 = 0.f;
#pragma unroll 8
        for (int d4 = 0; d4 < D_ / 4; ++d4) {
            int d = d4 * 4;
            float a0 = Ap[(size_t)(d + 0) * D_ + t];
            float a1 = Ap[(size_t)(d + 1) * D_ + t];
            float a2 = Ap[(size_t)(d + 2) * D_ + t];
            float a3 = Ap[(size_t)(d + 3) * D_ + t];
            float4 x0 = xs[0][d4], x1 = xs[1][d4], x2 = xs[2][d4], x3 = xs[3][d4];
            s0 = fmaf(x0.x, a0, s0); s0 = fmaf(x0.y, a1, s0);
            s0 = fmaf(x0.z, a2, s0); s0 = fmaf(x0.w, a3, s0);
            s1 = fmaf(x1.x, a0, s1); s1 = fmaf(x1.y, a1, s1);
            s1 = fmaf(x1.z, a2, s1); s1 = fmaf(x1.w, a3, s1);
            s2 = fmaf(x2.x, a0, s2); s2 = fmaf(x2.y, a1, s2);
            s2 = fmaf(x2.z, a2, s2); s2 = fmaf(x2.w, a3, s2);
            s3 = fmaf(x3.x, a0, s3); s3 = fmaf(x3.y, a1, s3);
            s3 = fmaf(x3.z, a2, s3); s3 = fmaf(x3.w, a3, s3);
        }
        ts[0 * D_ + t] = s0;   // conflict-free: consecutive threads, consecutive banks
        ts[1 * D_ + t] = s1;
        ts[2 * D_ + t] = s2;
        ts[3 * D_ + t] = s3;
    }
    __syncthreads();

    // ---- Stage B: thread t -> (m = t&127, row-pair rp = t>>7) ----
    {
        int m  = t & 127;
        int rp = t >> 7;             // handles rows 2*rp and 2*rp+1
        const float4* y = Y4 + (size_t)(b * M_ + m) * (D_ / 4);
        float u0 = 0.f, u1 = 0.f;
#pragma unroll 8
        for (int i = 0; i < D_ / 4; ++i) {
            float4 yv = y[i];
            float4 t0 = ts4[2 * rp + 0][i];   // warp-uniform address: smem broadcast
            float4 t1 = ts4[2 * rp + 1][i];
            u0 = fmaf(t0.x, yv.x, u0); u0 = fmaf(t0.y, yv.y, u0);
            u0 = fmaf(t0.z, yv.z, u0); u0 = fmaf(t0.w, yv.w, u0);
            u1 = fmaf(t1.x, yv.x, u1); u1 = fmaf(t1.y, yv.y, u1);
            u1 = fmaf(t1.z, yv.z, u1); u1 = fmaf(t1.w, yv.w, u1);
        }
        float bb = bias[0];
        S[(size_t)(r0 + 2 * rp + 0) * M_ + m] = u0 + bb;
        S[(size_t)(r0 + 2 * rp + 1) * M_ + m] = u1 + bb;
    }
}

// ---------------------------------------------------------------------------
extern "C" void kernel_launch(void* const* d_in, const int* in_sizes, int n_in,
                              void* d_out, int out_size)
{
    const float* X  = (const float*)d_in[0];   // [4,128,256]
    const float* Y  = (const float*)d_in[1];   // [4,128,256]
    const float* A  = (const float*)d_in[2];   // [256,256,1024]
    const float* W  = (const float*)d_in[3];   // [1,1024]
    const float* bb = (const float*)d_in[4];   // [1]
    float* S = (float*)d_out;                  // [4,128,128]

    float* Ap;  cudaGetSymbolAddress((void**)&Ap, g_Aprime);

    // K1: 65536 rows, 2 per warp, 8 warps/block -> 4096 blocks
    k1_fold_w<<<(D_ * D_) / 16, 256>>>((const float4*)A, (const float4*)W, Ap);
    // Fused K2+K3: 512 rows, 4 per block -> 128 blocks
    k23_fused<<<(B_ * N_) / 4, 256>>>((const float4*)X, Ap, (const float4*)Y, bb, S);
}

// round 4
// speedup vs baseline: 1.2200x; 1.0324x over previous
#include <cuda_runtime.h>

// Shapes (fixed by the problem)
#define B_   4
#define N_   128
#define M_   128
#define D_   256
#define BD_  1024
#define R_   (B_ * N_)        // 512 flattened (b,n) rows

#define ETILE   4             // e columns per block
#define DCHUNK  32            // d rows per block
#define NDC     (D_ / DCHUNK) // 8 d-chunks

// Scratch (no cudaMalloc allowed). 8 disjoint partial-T buffers: deterministic,
// no atomics, no zeroing. T[r][e] = sum_dc g_Tpart[dc][r][e].
__device__ float g_Tpart[NDC][R_][D_];    // 4 MB

// ---------------------------------------------------------------------------
// Kernel F: fused W-fold + partial X-contraction, overlapped with the 268 MB
// A stream (the HBM-roofline phase).
// Block (ex, dc) handles e in [ex*4, ex*4+4), d in [dc*32, dc*32+32):
//   phase 1: stream A[d, e, :] rows (512 KB), dot with W -> As[4][32] in smem
//   phase 2: pT[r, e'] = sum_{d in chunk} X[r, d] * As[e'][d]  -> g_Tpart[dc]
// grid = (64, 8) = 512 blocks, 256 threads. FMA work hides under DRAM stream.
// ---------------------------------------------------------------------------
__global__ __launch_bounds__(256) void kF(
    const float4* __restrict__ A4,   // [65536 rows][256 float4]
    const float4* __restrict__ W4,   // [256 float4]
    const float4* __restrict__ X4)   // [512 rows][64 float4]
{
    __shared__ float4 ws[BD_ / 4];           // 4 KB: W
    __shared__ float  As[ETILE][DCHUNK];     // 512 B: A'[e'][d_local]

    int t = threadIdx.x, lane = t & 31, w = t >> 5;
    ws[t] = W4[t];
    __syncthreads();

    int e0 = blockIdx.x * ETILE;
    int d0 = blockIdx.y * DCHUNK;

    // 128 (d,e) rows per block; local row lr -> (d_local = lr>>2, e' = lr&3).
    // Warp w: lr in [w*16, w*16+16), processed in pairs for MLP.
#pragma unroll
    for (int j = 0; j < 8; ++j) {
        int lr0 = w * 16 + 2 * j;            // even: pair shares d_local
        int dl  = lr0 >> 2;
        int ea  = e0 + (lr0 & 3);
        const float4* ra = A4 + (size_t)((d0 + dl) * D_ + ea) * (BD_ / 4);
        const float4* rb = ra + (BD_ / 4);   // e + 1: adjacent A row

        float s0 = 0.f, s1 = 0.f;
#pragma unroll
        for (int i = 0; i < 8; ++i) {
            float4 a0 = __ldcs(&ra[lane + i * 32]);
            float4 a1 = __ldcs(&rb[lane + i * 32]);
            float4 wv = ws[lane + i * 32];
            s0 += a0.x * wv.x + a0.y * wv.y + a0.z * wv.z + a0.w * wv.w;
            s1 += a1.x * wv.x + a1.y * wv.y + a1.z * wv.z + a1.w * wv.w;
        }
#pragma unroll
        for (int o = 16; o > 0; o >>= 1) {
            s0 += __shfl_xor_sync(0xFFFFFFFFu, s0, o);
            s1 += __shfl_xor_sync(0xFFFFFFFFu, s1, o);
        }
        if (lane == 0) {
            As[lr0 & 3][dl]       = s0;
            As[(lr0 & 3) + 1][dl] = s1;
        }
    }
    __syncthreads();

    // ---- phase 2: partial T. thread t handles r = t and r = t + 256 ----
    float acc0[ETILE] = {0.f, 0.f, 0.f, 0.f};
    float acc1[ETILE] = {0.f, 0.f, 0.f, 0.f};
    const float4* xr0 = X4 + (size_t)t * (D_ / 4) + d0 / 4;
    const float4* xr1 = xr0 + (size_t)256 * (D_ / 4);
#pragma unroll
    for (int i = 0; i < DCHUNK / 4; ++i) {   // 8 iters
        float4 x0 = xr0[i];
        float4 x1 = xr1[i];
#pragma unroll
        for (int ep = 0; ep < ETILE; ++ep) {
            float a0 = As[ep][4 * i + 0];
            float a1 = As[ep][4 * i + 1];
            float a2 = As[ep][4 * i + 2];
            float a3 = As[ep][4 * i + 3];
            acc0[ep] = fmaf(x0.x, a0, acc0[ep]);
            acc0[ep] = fmaf(x0.y, a1, acc0[ep]);
            acc0[ep] = fmaf(x0.z, a2, acc0[ep]);
            acc0[ep] = fmaf(x0.w, a3, acc0[ep]);
            acc1[ep] = fmaf(x1.x, a0, acc1[ep]);
            acc1[ep] = fmaf(x1.y, a1, acc1[ep]);
            acc1[ep] = fmaf(x1.z, a2, acc1[ep]);
            acc1[ep] = fmaf(x1.w, a3, acc1[ep]);
        }
    }
    float4 o0 = make_float4(acc0[0], acc0[1], acc0[2], acc0[3]);
    float4 o1 = make_float4(acc1[0], acc1[1], acc1[2], acc1[3]);
    *(float4*)&g_Tpart[blockIdx.y][t      ][e0] = o0;
    *(float4*)&g_Tpart[blockIdx.y][t + 256][e0] = o1;
}

// ---------------------------------------------------------------------------
// Kernel G: S[r, m] = sum_e T[r,e] * Y[b,m,e] + bias, T = sum of 8 partials.
// 256 blocks x 256 threads; block = 2 r-rows (same b). Thread (m = t&127,
// h = t>>7) covers e-half h for BOTH rows -> Y read exactly once per block.
// ---------------------------------------------------------------------------
__global__ __launch_bounds__(256) void kG(
    const float* __restrict__ Y,     // [B*128, 256]
    const float* __restrict__ bias,  // [1]
    float* __restrict__ S)           // [512, 128]
{
    int r0 = blockIdx.x * 2;
    int b  = r0 >> 7;
    int t  = threadIdx.x;

    __shared__ float ts[2][D_];      // summed T rows, 2 KB
    {
        int e = t;                   // 0..255, coalesced over e
        float v0 = 0.f, v1 = 0.f;
#pragma unroll
        for (int dc = 0; dc < NDC; ++dc) {
            v0 += g_Tpart[dc][r0 + 0][e];
            v1 += g_Tpart[dc][r0 + 1][e];
        }
        ts[0][e] = v0;
        ts[1][e] = v1;
    }
    __syncthreads();

    int m = t & 127;
    int h = t >> 7;                  // e-half: [h*128, h*128+128)
    const float4* y = (const float4*)(Y + ((size_t)(b * M_ + m)) * D_ + h * 128);

    float u0 = 0.f, u1 = 0.f;
#pragma unroll 8
    for (int i = 0; i < 32; ++i) {   // 128 e values
        float4 yv = y[i];
        int e = h * 128 + 4 * i;
        float t00 = ts[0][e], t01 = ts[0][e+1], t02 = ts[0][e+2], t03 = ts[0][e+3];
        float t10 = ts[1][e], t11 = ts[1][e+1], t12 = ts[1][e+2], t13 = ts[1][e+3];
        u0 = fmaf(t00, yv.x, u0); u0 = fmaf(t01, yv.y, u0);
        u0 = fmaf(t02, yv.z, u0); u0 = fmaf(t03, yv.w, u0);
        u1 = fmaf(t10, yv.x, u1); u1 = fmaf(t11, yv.y, u1);
        u1 = fmaf(t12, yv.z, u1); u1 = fmaf(t13, yv.w, u1);
    }

    __shared__ float pp[2][2][128];  // [row][half][m]
    pp[0][h][m] = u0;
    pp[1][h][m] = u1;
    __syncthreads();

    {   // combine halves: thread t -> (row = t>>7, m = t&127)
        int rr = t >> 7;
        float s = pp[rr][0][m] + pp[rr][1][m] + bias[0];
        S[(size_t)(r0 + rr) * M_ + m] = s;
    }
}

// ---------------------------------------------------------------------------
extern "C" void kernel_launch(void* const* d_in, const int* in_sizes, int n_in,
                              void* d_out, int out_size)
{
    const float* X  = (const float*)d_in[0];   // [4,128,256]
    const float* Y  = (const float*)d_in[1];   // [4,128,256]
    const float* A  = (const float*)d_in[2];   // [256,256,1024]
    const float* W  = (const float*)d_in[3];   // [1,1024]
    const float* bb = (const float*)d_in[4];   // [1]
    float* S = (float*)d_out;                  // [4,128,128]

    dim3 gridF(D_ / ETILE, NDC);               // (64, 8) = 512 blocks
    kF<<<gridF, 256>>>((const float4*)A, (const float4*)W, (const float4*)X);
    kG<<<R_ / 2, 256>>>(Y, bb, S);
}

// round 5
// speedup vs baseline: 1.4724x; 1.2069x over previous
#include <cuda_runtime.h>

// Shapes (fixed by the problem)
#define B_   4
#define N_   128
#define M_   128
#define D_   256
#define BD_  1024
#define R_   (B_ * N_)        // 512 flattened (b,n) rows

// Scratch (no cudaMalloc allowed)
__device__ float g_Aprime[D_ * D_];   // 256 KB: A'[d,e] = sum_k A[d,e,k]*W[k]
__device__ float g_T[R_ * D_];        // 512 KB: T[r,e] = X[r,:] @ A'

// ---------------------------------------------------------------------------
// Kernel 1: A'[row] = dot(A[row, :], W[:]); row = d*256 + e.
// Two CONSECUTIVE rows per warp, consecutive blocks -> linear 268 MB DRAM
// stream (this ordering measured fastest: 81% DRAM). __ldcs = evict-first.
// ---------------------------------------------------------------------------
__global__ __launch_bounds__(256) void k1_fold_w(
    const float4* __restrict__ A4,   // [65536 rows][256 float4]
    const float4* __restrict__ W4,   // [256 float4]
    float* __restrict__ Ap)          // [65536]
{
    __shared__ float4 ws[BD_ / 4];   // 4 KB
    ws[threadIdx.x] = W4[threadIdx.x];
    __syncthreads();

    int warp = (blockIdx.x * blockDim.x + threadIdx.x) >> 5;   // 0..32767
    int lane = threadIdx.x & 31;
    const float4* row0 = A4 + (size_t)(2 * warp) * (BD_ / 4);
    const float4* row1 = row0 + (BD_ / 4);

    float s0 = 0.0f, s1 = 0.0f;
#pragma unroll
    for (int i = 0; i < 8; ++i) {
        float4 a0 = __ldcs(&row0[lane + i * 32]);
        float4 a1 = __ldcs(&row1[lane + i * 32]);
        float4 w  = ws[lane + i * 32];
        s0 += a0.x * w.x + a0.y * w.y + a0.z * w.z + a0.w * w.w;
        s1 += a1.x * w.x + a1.y * w.y + a1.z * w.z + a1.w * w.w;
    }
#pragma unroll
    for (int o = 16; o > 0; o >>= 1) {
        s0 += __shfl_xor_sync(0xFFFFFFFFu, s0, o);
        s1 += __shfl_xor_sync(0xFFFFFFFFu, s1, o);
    }
    if (lane == 0) {
        Ap[2 * warp + 0] = s0;
        Ap[2 * warp + 1] = s1;
    }
}

// ---------------------------------------------------------------------------
// Kernel 2': T[r,e] = sum_d X[r,d] * A'[d,e].
// Grid (64 r-tiles x 2 e-halves) = 128 blocks, 1024 threads (32 warps/block
// -> high occupancy). Thread: e = eh*128 + (tid&127), dq = tid>>7 splits the
// d-depth 8 ways (32 d each). 8 r-accumulators; smem reduction over dq.
// ---------------------------------------------------------------------------
__global__ __launch_bounds__(1024) void k2_xa(
    const float4* __restrict__ X4,   // [512][64] float4
    const float* __restrict__ Ap,    // [256*256]
    float* __restrict__ T)           // [512*256]
{
    int rx = blockIdx.x;             // 0..63 -> rows r0..r0+7
    int eh = blockIdx.y;             // 0..1  -> e half
    int r0 = rx * 8;
    int tid = threadIdx.x;

    __shared__ float  xs[8][D_];             // 8 KB  X tile
    __shared__ float  ps[8][8][128];         // 32 KB partials [dq][r][e-local]

    // cooperative X tile load: 8 rows x 64 float4 = 512 float4
    if (tid < 512) {
        int ri = tid >> 6, c = tid & 63;
        float4 v = X4[(size_t)(r0 + ri) * (D_ / 4) + c];
        xs[ri][4 * c + 0] = v.x;
        xs[ri][4 * c + 1] = v.y;
        xs[ri][4 * c + 2] = v.z;
        xs[ri][4 * c + 3] = v.w;
    }
    __syncthreads();

    int el = tid & 127;              // e-local
    int e  = eh * 128 + el;
    int dq = tid >> 7;               // 0..7
    int d0 = dq * 32;

    float acc[8] = {0,0,0,0,0,0,0,0};
#pragma unroll 8
    for (int i = 0; i < 32; ++i) {
        int d = d0 + i;
        float a = Ap[(size_t)d * D_ + e];    // coalesced, L2-resident
#pragma unroll
        for (int r = 0; r < 8; ++r)
            acc[r] = fmaf(xs[r][d], a, acc[r]);
    }
#pragma unroll
    for (int r = 0; r < 8; ++r)
        ps[dq][r][el] = acc[r];
    __syncthreads();

    // reduce: 1024 outputs (8r x 128e); thread -> (r = tid>>7, e-local = tid&127)
    {
        int r  = tid >> 7;
        int ee = tid & 127;
        float s = 0.f;
#pragma unroll
        for (int q = 0; q < 8; ++q)
            s += ps[q][r][ee];
        T[(size_t)(r0 + r) * D_ + eh * 128 + ee] = s;
    }
}

// ---------------------------------------------------------------------------
// Kernel 3': S[r,m] = sum_e T[r,e] * Y[b,m,e] + bias.
// 256 blocks (2 r-rows each) x 1024 threads. Thread: m = tid>>3, eo = tid&7;
// each thread covers 32 e-values (float4s strided by 8) for both rows, then
// warp-shuffle reduce over eo (low lane bits) -> no smem reduction round trip.
// Y[b] (128 KB) read exactly once per block.
// ---------------------------------------------------------------------------
__global__ __launch_bounds__(1024) void k3_ty(
    const float4* __restrict__ T4,   // [512][64] float4
    const float4* __restrict__ Y4,   // [512][64] float4
    const float* __restrict__ bias,  // [1]
    float* __restrict__ S)           // [512*128]
{
    int r0 = blockIdx.x * 2;
    int b  = r0 >> 7;
    int tid = threadIdx.x;

    __shared__ float4 ts[2][D_ / 4]; // 2 KB  T rows
    if (tid < 128) {
        int ri = tid >> 6, c = tid & 63;
        ts[ri][c] = T4[(size_t)(r0 + ri) * (D_ / 4) + c];
    }
    __syncthreads();

    int m  = tid >> 3;               // 0..127
    int eo = tid & 7;                // 0..7
    const float4* y = Y4 + (size_t)(b * M_ + m) * (D_ / 4);

    float u0 = 0.f, u1 = 0.f;
#pragma unroll
    for (int k = 0; k < 8; ++k) {
        int c = eo + k * 8;          // float4 index 0..63, coalesced across eo
        float4 yv = y[c];
        float4 t0 = ts[0][c];
        float4 t1 = ts[1][c];
        u0 = fmaf(t0.x, yv.x, u0); u0 = fmaf(t0.y, yv.y, u0);
        u0 = fmaf(t0.z, yv.z, u0); u0 = fmaf(t0.w, yv.w, u0);
        u1 = fmaf(t1.x, yv.x, u1); u1 = fmaf(t1.y, yv.y, u1);
        u1 = fmaf(t1.z, yv.z, u1); u1 = fmaf(t1.w, yv.w, u1);
    }
    // reduce across eo (lane bits 0..2)
#pragma unroll
    for (int o = 4; o > 0; o >>= 1) {
        u0 += __shfl_xor_sync(0xFFFFFFFFu, u0, o);
        u1 += __shfl_xor_sync(0xFFFFFFFFu, u1, o);
    }
    if (eo == 0) {
        float bb = bias[0];
        S[(size_t)(r0 + 0) * M_ + m] = u0 + bb;
        S[(size_t)(r0 + 1) * M_ + m] = u1 + bb;
    }
}

// ---------------------------------------------------------------------------
extern "C" void kernel_launch(void* const* d_in, const int* in_sizes, int n_in,
                              void* d_out, int out_size)
{
    const float* X  = (const float*)d_in[0];   // [4,128,256]
    const float* Y  = (const float*)d_in[1];   // [4,128,256]
    const float* A  = (const float*)d_in[2];   // [256,256,1024]
    const float* W  = (const float*)d_in[3];   // [1,1024]
    const float* bb = (const float*)d_in[4];   // [1]
    float* S = (float*)d_out;                  // [4,128,128]

    float* Ap;  cudaGetSymbolAddress((void**)&Ap, g_Aprime);
    float* T;   cudaGetSymbolAddress((void**)&T,  g_T);

    // K1: 65536 rows, 2 per warp, 8 warps/block -> 4096 blocks (linear stream)
    k1_fold_w<<<(D_ * D_) / 16, 256>>>((const float4*)A, (const float4*)W, Ap);
    // K2': 64 r-tiles x 2 e-halves, 1024 threads
    dim3 g2(R_ / 8, 2);
    k2_xa<<<g2, 1024>>>((const float4*)X, Ap, T);
    // K3': 256 blocks (2 rows each), 1024 threads
    k3_ty<<<R_ / 2, 1024>>>((const float4*)T, (const float4*)Y, bb, S);
}

// round 6
// speedup vs baseline: 1.5296x; 1.0388x over previous
#include <cuda_runtime.h>

// Shapes (fixed by the problem)
#define B_   4
#define N_   128
#define M_   128
#define D_   256
#define BD_  1024
#define R_   (B_ * N_)        // 512 flattened (b,n) rows

// Scratch (no cudaMalloc allowed)
__device__ float g_Aprime[D_ * D_];   // 256 KB: A'[d,e] = sum_k A[d,e,k]*W[k]

// ---------------------------------------------------------------------------
// Kernel 1: A'[row] = dot(A[row, :], W[:]); row = d*256 + e.
// ONE row per warp (measured best: 81.2% DRAM, 42.3us), linear 268 MB stream,
// __ldcs evict-first, W staged in smem.
// ---------------------------------------------------------------------------
__global__ __launch_bounds__(256) void k1_fold_w(
    const float4* __restrict__ A4,   // [65536 rows][256 float4]
    const float4* __restrict__ W4,   // [256 float4]
    float* __restrict__ Ap)          // [65536]
{
    __shared__ float4 ws[BD_ / 4];   // 4 KB
    ws[threadIdx.x] = W4[threadIdx.x];
    __syncthreads();

    int warp = (blockIdx.x * blockDim.x + threadIdx.x) >> 5;   // 0..65535
    int lane = threadIdx.x & 31;
    const float4* row = A4 + (size_t)warp * (BD_ / 4);

    float s = 0.0f;
#pragma unroll
    for (int i = 0; i < 8; ++i) {
        float4 a = __ldcs(&row[lane + i * 32]);
        float4 w = ws[lane + i * 32];
        s += a.x * w.x + a.y * w.y;
        s += a.z * w.z + a.w * w.w;
    }
#pragma unroll
    for (int o = 16; o > 0; o >>= 1)
        s += __shfl_xor_sync(0xFFFFFFFFu, s, o);
    if (lane == 0) Ap[warp] = s;
}

// ---------------------------------------------------------------------------
// Fused tail: per block, 4 r-rows (same b), 1024 threads (32 warps).
//  Stage A: T[4][256] = X_tile @ A'.  Thread (e = tid&255, dq = tid>>2&... )
//           4-way d-split (64 d each), smem partials, tree-free reduce.
//           A' L2 traffic: 128 blocks x 256 KB = 32 MB.
//  Stage B: S[4][128] = T @ Y[b]^T + bias.  Thread (m = tid>>3, eo = tid&7),
//           8-way e-split, warp-shuffle reduce over eo (lane bits 0..2).
//           Y[b] read exactly once per block: 16 MB L2 total.
// ---------------------------------------------------------------------------
__global__ __launch_bounds__(1024) void k23_fused(
    const float4* __restrict__ X4,   // [512][64] float4
    const float* __restrict__ Ap,    // [256*256]
    const float4* __restrict__ Y4,   // [512][64] float4
    const float* __restrict__ bias,  // [1]
    float* __restrict__ S)           // [512*128]
{
    int r0 = blockIdx.x * 4;
    int b  = r0 >> 7;
    int tid = threadIdx.x;

    __shared__ float  xs[4][D_];        // 4 KB  X tile
    __shared__ float  ps[4][4][D_];     // 16 KB partials [dq][r][e]
    __shared__ float4 ts4[4][D_ / 4];   // 4 KB  final T rows

    // cooperative X tile load: 4 rows x 64 float4
    if (tid < 256) {
        int ri = tid >> 6, c = tid & 63;
        float4 v = X4[(size_t)(r0 + ri) * (D_ / 4) + c];
        xs[ri][4 * c + 0] = v.x;
        xs[ri][4 * c + 1] = v.y;
        xs[ri][4 * c + 2] = v.z;
        xs[ri][4 * c + 3] = v.w;
    }
    __syncthreads();

    // ---- Stage A ----
    {
        int e  = tid & 255;
        int dq = tid >> 8;               // 0..3
        int d0 = dq * 64;
        float a0 = 0.f, a1 = 0.f, a2 = 0.f, a3 = 0.f;
#pragma unroll 8
        for (int i = 0; i < 64; ++i) {
            int d = d0 + i;
            float av = Ap[(size_t)d * D_ + e];   // coalesced over e, L2-resident
            float x0 = xs[0][d], x1 = xs[1][d], x2 = xs[2][d], x3 = xs[3][d];
            a0 = fmaf(x0, av, a0);
            a1 = fmaf(x1, av, a1);
            a2 = fmaf(x2, av, a2);
            a3 = fmaf(x3, av, a3);
        }
        ps[dq][0][e] = a0;
        ps[dq][1][e] = a1;
        ps[dq][2][e] = a2;
        ps[dq][3][e] = a3;
    }
    __syncthreads();

    // reduce over dq: thread -> (r = tid>>8, e = tid&255)
    {
        int r = tid >> 8;
        int e = tid & 255;
        float s = ps[0][r][e] + ps[1][r][e] + ps[2][r][e] + ps[3][r][e];
        ((float*)ts4)[r * D_ + e] = s;
    }
    __syncthreads();

    // ---- Stage B ----
    {
        int m  = tid >> 3;               // 0..127
        int eo = tid & 7;                // 0..7 (lane bits 0..2)
        const float4* y = Y4 + (size_t)(b * M_ + m) * (D_ / 4);

        float u0 = 0.f, u1 = 0.f, u2 = 0.f, u3 = 0.f;
#pragma unroll
        for (int k = 0; k < 8; ++k) {
            int c = eo + 8 * k;          // float4 index, coalesced across eo
            float4 yv = y[c];
            float4 t0 = ts4[0][c], t1 = ts4[1][c], t2 = ts4[2][c], t3 = ts4[3][c];
            u0 = fmaf(t0.x, yv.x, u0); u0 = fmaf(t0.y, yv.y, u0);
            u0 = fmaf(t0.z, yv.z, u0); u0 = fmaf(t0.w, yv.w, u0);
            u1 = fmaf(t1.x, yv.x, u1); u1 = fmaf(t1.y, yv.y, u1);
            u1 = fmaf(t1.z, yv.z, u1); u1 = fmaf(t1.w, yv.w, u1);
            u2 = fmaf(t2.x, yv.x, u2); u2 = fmaf(t2.y, yv.y, u2);
            u2 = fmaf(t2.z, yv.z, u2); u2 = fmaf(t2.w, yv.w, u2);
            u3 = fmaf(t3.x, yv.x, u3); u3 = fmaf(t3.y, yv.y, u3);
            u3 = fmaf(t3.z, yv.z, u3); u3 = fmaf(t3.w, yv.w, u3);
        }
#pragma unroll
        for (int o = 4; o > 0; o >>= 1) {
            u0 += __shfl_xor_sync(0xFFFFFFFFu, u0, o);
            u1 += __shfl_xor_sync(0xFFFFFFFFu, u1, o);
            u2 += __shfl_xor_sync(0xFFFFFFFFu, u2, o);
            u3 += __shfl_xor_sync(0xFFFFFFFFu, u3, o);
        }
        if (eo == 0) {
            float bb = bias[0];
            S[(size_t)(r0 + 0) * M_ + m] = u0 + bb;
            S[(size_t)(r0 + 1) * M_ + m] = u1 + bb;
            S[(size_t)(r0 + 2) * M_ + m] = u2 + bb;
            S[(size_t)(r0 + 3) * M_ + m] = u3 + bb;
        }
    }
}

// ---------------------------------------------------------------------------
extern "C" void kernel_launch(void* const* d_in, const int* in_sizes, int n_in,
                              void* d_out, int out_size)
{
    const float* X  = (const float*)d_in[0];   // [4,128,256]
    const float* Y  = (const float*)d_in[1];   // [4,128,256]
    const float* A  = (const float*)d_in[2];   // [256,256,1024]
    const float* W  = (const float*)d_in[3];   // [1,1024]
    const float* bb = (const float*)d_in[4];   // [1]
    float* S = (float*)d_out;                  // [4,128,128]

    float* Ap;  cudaGetSymbolAddress((void**)&Ap, g_Aprime);

    // K1: 65536 rows, 1 per warp, 8 warps/block -> 8192 blocks
    k1_fold_w<<<(D_ * D_) / 8, 256>>>((const float4*)A, (const float4*)W, Ap);
    // Fused tail: 128 blocks x 1024 threads
    k23_fused<<<R_ / 4, 1024>>>((const float4*)X, Ap, (const float4*)Y, bb, S);
}